// round 6
// baseline (speedup 1.0000x reference)
#include <cuda_runtime.h>
#include <cstdint>

#define NN 768
#define DD 64
#define LN_EPS 1e-5f

__device__ float g_A[NN * DD];  // h[i] @ W_g[64:128]
__device__ float g_B[NN * DD];  // h[j] @ W_g[128:192] + b_g
__device__ float g_S[9];        // LN(z) moment scalars (scaled by 1/64)

#define FFMA2(d, a, b) asm("fma.rn.f32x2 %0, %1, %2, %0;" : "+l"(d) : "l"(a), "l"(b))
#define PACK2(dst, lo, hi) asm("mov.b64 %0, {%1, %2};" : "=l"(dst) : "f"(lo), "f"(hi))
#define DUP2(dst, v)       asm("mov.b64 %0, {%1, %1};" : "=l"(dst) : "f"(v))
#define UNPACK2(lo, hi, v) asm("mov.b64 {%0, %1}, %2;" : "=f"(lo), "=f"(hi) : "l"(v))

// ---------------------------------------------------------------------------
// Precompute A[i,d], B[i,d], and the 9 LN(z) moment scalars
// ---------------------------------------------------------------------------
__global__ __launch_bounds__(DD) void precompute_kernel(
    const float* __restrict__ h,
    const float* __restrict__ W_g,
    const float* __restrict__ b_g,
    const float* __restrict__ W_r,
    const float* __restrict__ b_r)
{
    __shared__ float hs[DD];
    const int i = blockIdx.x;
    const int d = threadIdx.x;
    hs[d] = h[i * DD + d];
    __syncthreads();
    float a = 0.f, b = 0.f;
#pragma unroll 16
    for (int k = 0; k < DD; k++) {
        float hv = hs[k];
        a = fmaf(hv, W_g[(64 + k) * DD + d], a);
        b = fmaf(hv, W_g[(128 + k) * DD + d], b);
    }
    g_A[i * DD + d] = a;
    g_B[i * DD + d] = b + b_g[d];

    // Block 0: moment scalars for LN(corr @ W_r + b_r)
    if (i == 0) {
        const float w0 = W_r[d], w1 = W_r[64 + d], bb = b_r[d];
        float v[9] = { w0, w1, bb, w0 * w0, w1 * w1, w0 * w1,
                       w0 * bb, w1 * bb, bb * bb };
        __shared__ float red[2][9];
#pragma unroll
        for (int s = 0; s < 9; s++) {
            float x = v[s];
#pragma unroll
            for (int off = 16; off; off >>= 1)
                x += __shfl_xor_sync(0xffffffffu, x, off);
            v[s] = x;
        }
        if ((d & 31) == 0) {
#pragma unroll
            for (int s = 0; s < 9; s++) red[d >> 5][s] = v[s];
        }
        __syncthreads();
        if (d < 9) g_S[d] = (red[0][d] + red[1][d]) * (1.f / 64.f);
    }
}

struct Smem {
    ulonglong2         wsm2[32][32];      // [k2][l]: ((w[2k2][l],w[2k2][l+32]),(w[2k2+1][l],w[2k2+1][l+32]))
    unsigned long long Rsm[8][8][64];     // [warp][jj][k] = (r[k], r[k]) duplicated
    int   list[832];
    int   warp_tot[8], warp_off[8], mcount;
    float sh_acc[8][64];
    float sh_hs[64], sh_y[64];
};

// ---------------------------------------------------------------------------
// Main kernel: one block per row i; warps process chunks of 8 masked pairs.
// Lane owns output dims d=lane and d+32 (packed as f32x2).
// ---------------------------------------------------------------------------
__global__ __launch_bounds__(256) void gatraj_main_kernel(
    const float* __restrict__ corr,   // [N,N,2]
    const int*   __restrict__ nei,    // [N,N]
    const float* __restrict__ h,      // [N,D]
    const float* __restrict__ cn,     // [N,D]
    const float* __restrict__ W_r,    // [2,D]
    const float* __restrict__ b_r,
    const float* __restrict__ g_r,
    const float* __restrict__ be_r,
    const float* __restrict__ W_g,    // [3D,D] rows 0..63
    const float* __restrict__ g_g,
    const float* __restrict__ be_g,
    const float* __restrict__ be_a,   // [1]
    const float* __restrict__ W_w,    // [D,D]
    const float* __restrict__ b_w,
    const float* __restrict__ g_w,
    const float* __restrict__ be_w,
    float* __restrict__ out)          // [2*N*D]: H_out then C
{
    extern __shared__ char smem_raw[];
    Smem* S = (Smem*)smem_raw;

    const int i    = blockIdx.x;
    const int tid  = threadIdx.x;
    const int warp = tid >> 5;
    const int lane = tid & 31;

    const int* neirow = nei + (size_t)i * NN;

    // ---- Stage Wg_r as packed column-pair quads ----
    for (int idx = tid; idx < 32 * 32; idx += 256) {
        const int k2 = idx >> 5, l = idx & 31;
        unsigned long long w0, w1;
        PACK2(w0, W_g[(2 * k2) * DD + l],     W_g[(2 * k2) * DD + l + 32]);
        PACK2(w1, W_g[(2 * k2 + 1) * DD + l], W_g[(2 * k2 + 1) * DD + l + 32]);
        ulonglong2 q; q.x = w0; q.y = w1;
        S->wsm2[k2][l] = q;
    }

    // ---- Deterministic compaction of masked j (sorted order) ----
    {
        const int b3 = tid * 3;
        const int m0 = neirow[b3 + 0] > 0;
        const int m1 = neirow[b3 + 1] > 0;
        const int m2 = neirow[b3 + 2] > 0;
        const int c  = m0 + m1 + m2;
        int s = c;
#pragma unroll
        for (int off = 1; off < 32; off <<= 1) {
            int v = __shfl_up_sync(0xffffffffu, s, off);
            if (lane >= off) s += v;
        }
        if (lane == 31) S->warp_tot[warp] = s;
        __syncthreads();
        if (tid == 0) {
            int run = 0;
#pragma unroll
            for (int w = 0; w < 8; w++) { S->warp_off[w] = run; run += S->warp_tot[w]; }
            S->mcount = run;
        }
        __syncthreads();
        int pos = S->warp_off[warp] + s - c;
        if (m0) S->list[pos++] = b3 + 0;
        if (m1) S->list[pos++] = b3 + 1;
        if (m2) S->list[pos++] = b3 + 2;
        const int mc  = S->mcount;
        const int pad = (mc + 63) & ~63;
        for (int idx = mc + tid; idx < pad; idx += 256) S->list[idx] = 0;
    }
    __syncthreads();
    const int mcount = S->mcount;

    // ---- Per-thread constants ----
    const float wr0_lo = W_r[lane],        wr0_hi = W_r[lane + 32];
    const float wr1_lo = W_r[64 + lane],   wr1_hi = W_r[64 + lane + 32];
    const float br_lo  = b_r[lane],        br_hi  = b_r[lane + 32];
    const float gr_lo  = g_r[lane],        gr_hi  = g_r[lane + 32];
    const float ber_lo = be_r[lane],       ber_hi = be_r[lane + 32];
    const float gg_lo  = g_g[lane],        gg_hi  = g_g[lane + 32];
    const float beg_lo = be_g[lane],       beg_hi = be_g[lane + 32];
    const float A_lo   = g_A[i * DD + lane];
    const float A_hi   = g_A[i * DD + lane + 32];
    // analytic LN(z) moment scalars
    const float S0 = g_S[0], S1 = g_S[1], Sb = g_S[2];
    const float Q00 = g_S[3], Q11 = g_S[4], Q01 = g_S[5];
    const float Q0b = g_S[6], Q1b = g_S[7], Qbb = g_S[8];

    const float2* corr2 = (const float2*)corr + (size_t)i * NN;

    float acc_lo = 0.f, acc_hi = 0.f;

    for (int base = warp * 8; base < mcount; base += 64) {
        unsigned long long yv[8];

        // ---- Phase 1: r vectors (analytic LN), pre-duplicated -> shared ----
#pragma unroll
        for (int jj = 0; jj < 8; jj++) {
            const int j = S->list[base + jj];
            const float2 c = corr2[j];
            const float z_lo = fmaf(c.x, wr0_lo, fmaf(c.y, wr1_lo, br_lo));
            const float z_hi = fmaf(c.x, wr0_hi, fmaf(c.y, wr1_hi, br_hi));
            const float u   = fmaf(c.x, S0, fmaf(c.y, S1, Sb));
            const float ez2 = fmaf(c.x * c.x, Q00,
                              fmaf(c.y * c.y, Q11,
                              fmaf(2.f * c.x * c.y, Q01,
                              fmaf(2.f * c.x, Q0b,
                              fmaf(2.f * c.y, Q1b, Qbb)))));
            const float rstd = rsqrtf(fmaxf(ez2 - u * u, 0.f) + LN_EPS);
            const float r_lo = fmaxf(fmaf(gr_lo * (z_lo - u), rstd, ber_lo), 0.f);
            const float r_hi = fmaxf(fmaf(gr_hi * (z_hi - u), rstd, ber_hi), 0.f);
            unsigned long long d0, d1;
            DUP2(d0, r_lo);
            DUP2(d1, r_hi);
            S->Rsm[warp][jj][lane]      = d0;
            S->Rsm[warp][jj][lane + 32] = d1;
            PACK2(yv[jj], A_lo + g_B[j * DD + lane], A_hi + g_B[j * DD + lane + 32]);
        }
        __syncwarp();

        // ---- Phase 2: y[jj] += r[jj] @ Wg_r (pure LDS.128 + FFMA2, no MOVs) ----
#pragma unroll 4
        for (int k2 = 0; k2 < 32; k2++) {
            const ulonglong2 w = S->wsm2[k2][lane];
#pragma unroll
            for (int jj = 0; jj < 8; jj++) {
                const ulonglong2 r = *(const ulonglong2*)&S->Rsm[warp][jj][k2 * 2];
                FFMA2(yv[jj], r.x, w.x);
                FFMA2(yv[jj], r.y, w.y);
            }
        }
        __syncwarp();

        // ---- Phase 3: LN + sigmoid gate + accumulate ----
#pragma unroll
        for (int jj = 0; jj < 8; jj++) {
            if (base + jj >= mcount) break;    // warp-uniform
            float y_lo, y_hi;
            UNPACK2(y_lo, y_hi, yv[jj]);
            float s1 = y_lo + y_hi;
            float s2 = y_lo * y_lo + y_hi * y_hi;
#pragma unroll
            for (int off = 16; off; off >>= 1) {
                s1 += __shfl_xor_sync(0xffffffffu, s1, off);
                s2 += __shfl_xor_sync(0xffffffffu, s2, off);
            }
            const float u    = s1 * (1.f / 64.f);
            const float rstd = rsqrtf(fmaxf(s2 * (1.f / 64.f) - u * u, 0.f) + LN_EPS);
            const float t_lo = fmaf(gg_lo * (y_lo - u), rstd, beg_lo);
            const float t_hi = fmaf(gg_hi * (y_hi - u), rstd, beg_hi);
            const float gate_lo = 1.f / (1.f + __expf(-t_lo));
            const float gate_hi = 1.f / (1.f + __expf(-t_hi));
            const int j = S->list[base + jj];
            acc_lo = fmaf(h[j * DD + lane],      gate_lo, acc_lo);
            acc_hi = fmaf(h[j * DD + lane + 32], gate_hi, acc_hi);
        }
    }

    S->sh_acc[warp][lane]      = acc_lo;
    S->sh_acc[warp][lane + 32] = acc_hi;
    __syncthreads();

    // ---- Block reduce + Pos scale (Pos = 1/mcount if relu(be_a)>0 else 1/N) ----
    if (tid < 64) {
        float s = 0.f;
#pragma unroll
        for (int w = 0; w < 8; w++) s += S->sh_acc[w][tid];
        const float rba   = fmaxf(be_a[0], 0.f);
        const float scale = (rba > 0.f) ? (1.f / (float)(mcount > 0 ? mcount : 1))
                                        : (1.f / (float)NN);
        S->sh_hs[tid] = s * scale;
    }
    __syncthreads();

    // ---- Epilogue: relu(LN(H_sum @ W_w + b_w)) + cn; tanh ----
    if (tid < 64) {
        float y = b_w[tid];
#pragma unroll 16
        for (int k = 0; k < 64; k++)
            y = fmaf(S->sh_hs[k], W_w[k * DD + tid], y);
        S->sh_y[tid] = y;
    }
    __syncthreads();

    if (tid < 64) {
        float s1 = 0.f, s2 = 0.f;
#pragma unroll 16
        for (int k = 0; k < 64; k++) {
            const float v = S->sh_y[k];
            s1 += v;
            s2 += v * v;
        }
        const float u    = s1 * (1.f / 64.f);
        const float rstd = rsqrtf(fmaxf(s2 * (1.f / 64.f) - u * u, 0.f) + LN_EPS);
        const float y    = S->sh_y[tid];
        const float hsum = fmaxf(fmaf(g_w[tid] * (y - u), rstd, be_w[tid]), 0.f);
        const float Cv   = hsum + cn[i * DD + tid];
        const float Hout = h[i * DD + tid] + tanhf(Cv);
        out[i * DD + tid]           = Hout;
        out[NN * DD + i * DD + tid] = Cv;
    }
}

// ---------------------------------------------------------------------------
extern "C" void kernel_launch(void* const* d_in, const int* in_sizes, int n_in,
                              void* d_out, int out_size)
{
    const float* corr = (const float*)d_in[0];
    const int*   nei  = (const int*)d_in[1];
    const float* h    = (const float*)d_in[3];
    const float* cn   = (const float*)d_in[4];
    const float* W_r  = (const float*)d_in[5];
    const float* b_r  = (const float*)d_in[6];
    const float* g_r  = (const float*)d_in[7];
    const float* be_r = (const float*)d_in[8];
    const float* W_g  = (const float*)d_in[9];
    const float* b_g  = (const float*)d_in[10];
    const float* g_g  = (const float*)d_in[11];
    const float* be_g = (const float*)d_in[12];
    const float* be_a = (const float*)d_in[16];
    const float* W_w  = (const float*)d_in[17];
    const float* b_w  = (const float*)d_in[18];
    const float* g_w  = (const float*)d_in[19];
    const float* be_w = (const float*)d_in[20];
    float* out = (float*)d_out;

    const int smem_bytes = (int)sizeof(Smem);
    cudaFuncSetAttribute(gatraj_main_kernel,
                         cudaFuncAttributeMaxDynamicSharedMemorySize, smem_bytes);

    precompute_kernel<<<NN, DD>>>(h, W_g, b_g, W_r, b_r);
    gatraj_main_kernel<<<NN, 256, smem_bytes>>>(corr, nei, h, cn,
                                                W_r, b_r, g_r, be_r,
                                                W_g, g_g, be_g, be_a,
                                                W_w, b_w, g_w, be_w, out);
}

// round 7
// speedup vs baseline: 1.0692x; 1.0692x over previous
#include <cuda_runtime.h>
#include <cstdint>

#define NN 768
#define DD 64
#define LN_EPS 1e-5f

__device__ float g_A[NN * DD];  // h[i] @ W_g[64:128]
__device__ float g_B[NN * DD];  // h[j] @ W_g[128:192] + b_g
__device__ float g_S[9];        // LN(z) moment scalars (scaled by 1/64)

#define FFMA2(d, a, b) asm("fma.rn.f32x2 %0, %1, %2, %0;" : "+l"(d) : "l"(a), "l"(b))
#define PACK2(dst, lo, hi) asm("mov.b64 %0, {%1, %2};" : "=l"(dst) : "f"(lo), "f"(hi))
#define DUP2(dst, v)       asm("mov.b64 %0, {%1, %1};" : "=l"(dst) : "f"(v))
#define UNPACK2(lo, hi, v) asm("mov.b64 {%0, %1}, %2;" : "=f"(lo), "=f"(hi) : "l"(v))

// ---------------------------------------------------------------------------
// Precompute A[i,d], B[i,d], and the 9 LN(z) moment scalars
// ---------------------------------------------------------------------------
__global__ __launch_bounds__(DD) void precompute_kernel(
    const float* __restrict__ h,
    const float* __restrict__ W_g,
    const float* __restrict__ b_g,
    const float* __restrict__ W_r,
    const float* __restrict__ b_r)
{
    __shared__ float hs[DD];
    const int i = blockIdx.x;
    const int d = threadIdx.x;
    hs[d] = h[i * DD + d];
    __syncthreads();
    float a = 0.f, b = 0.f;
#pragma unroll 16
    for (int k = 0; k < DD; k++) {
        float hv = hs[k];
        a = fmaf(hv, W_g[(64 + k) * DD + d], a);
        b = fmaf(hv, W_g[(128 + k) * DD + d], b);
    }
    g_A[i * DD + d] = a;
    g_B[i * DD + d] = b + b_g[d];

    if (i == 0) {
        const float w0 = W_r[d], w1 = W_r[64 + d], bb = b_r[d];
        float v[9] = { w0, w1, bb, w0 * w0, w1 * w1, w0 * w1,
                       w0 * bb, w1 * bb, bb * bb };
        __shared__ float red[2][9];
#pragma unroll
        for (int s = 0; s < 9; s++) {
            float x = v[s];
#pragma unroll
            for (int off = 16; off; off >>= 1)
                x += __shfl_xor_sync(0xffffffffu, x, off);
            v[s] = x;
        }
        if ((d & 31) == 0) {
#pragma unroll
            for (int s = 0; s < 9; s++) red[d >> 5][s] = v[s];
        }
        __syncthreads();
        if (d < 9) g_S[d] = (red[0][d] + red[1][d]) * (1.f / 64.f);
    }
}

struct Smem {
    ulonglong2 wdup[64][32];    // [k][l]: ((w[k][l],w[k][l]),(w[k][l+32],w[k][l+32]))
    float      Rsm[8][4][128];  // [warp][jjpair][k*2+parity]
    int   list[832];
    int   warp_tot[8], warp_off[8], mcount;
    float sh_acc[8][64];
    float sh_hs[64], sh_y[64];
};

// ---------------------------------------------------------------------------
// Main kernel: one block per row i; warps process chunks of 8 masked pairs.
// f32x2 packing is ACROSS jj pairs (no operand duplication in the hot loop).
// ---------------------------------------------------------------------------
__global__ __launch_bounds__(256) void gatraj_main_kernel(
    const float* __restrict__ corr,   // [N,N,2]
    const int*   __restrict__ nei,    // [N,N]
    const float* __restrict__ h,      // [N,D]
    const float* __restrict__ cn,     // [N,D]
    const float* __restrict__ W_r,    // [2,D]
    const float* __restrict__ b_r,
    const float* __restrict__ g_r,
    const float* __restrict__ be_r,
    const float* __restrict__ W_g,    // [3D,D] rows 0..63
    const float* __restrict__ g_g,
    const float* __restrict__ be_g,
    const float* __restrict__ be_a,   // [1]
    const float* __restrict__ W_w,    // [D,D]
    const float* __restrict__ b_w,
    const float* __restrict__ g_w,
    const float* __restrict__ be_w,
    float* __restrict__ out)          // [2*N*D]: H_out then C
{
    extern __shared__ char smem_raw[];
    Smem* S = (Smem*)smem_raw;

    const int i    = blockIdx.x;
    const int tid  = threadIdx.x;
    const int warp = tid >> 5;
    const int lane = tid & 31;

    const int* neirow = nei + (size_t)i * NN;

    // ---- Stage Wg_r pre-duplicated: wdup[k][l] = ((wlo,wlo),(whi,whi)) ----
    for (int idx = tid; idx < 64 * 32; idx += 256) {
        const int k = idx >> 5, l = idx & 31;
        unsigned long long d0, d1;
        DUP2(d0, W_g[k * DD + l]);
        DUP2(d1, W_g[k * DD + l + 32]);
        ulonglong2 q; q.x = d0; q.y = d1;
        S->wdup[k][l] = q;
    }

    // ---- Deterministic compaction of masked j (sorted order) ----
    {
        const int b3 = tid * 3;
        const int m0 = neirow[b3 + 0] > 0;
        const int m1 = neirow[b3 + 1] > 0;
        const int m2 = neirow[b3 + 2] > 0;
        const int c  = m0 + m1 + m2;
        int s = c;
#pragma unroll
        for (int off = 1; off < 32; off <<= 1) {
            int v = __shfl_up_sync(0xffffffffu, s, off);
            if (lane >= off) s += v;
        }
        if (lane == 31) S->warp_tot[warp] = s;
        __syncthreads();
        if (tid == 0) {
            int run = 0;
#pragma unroll
            for (int w = 0; w < 8; w++) { S->warp_off[w] = run; run += S->warp_tot[w]; }
            S->mcount = run;
        }
        __syncthreads();
        int pos = S->warp_off[warp] + s - c;
        if (m0) S->list[pos++] = b3 + 0;
        if (m1) S->list[pos++] = b3 + 1;
        if (m2) S->list[pos++] = b3 + 2;
        const int mc  = S->mcount;
        const int pad = (mc + 63) & ~63;
        for (int idx = mc + tid; idx < pad; idx += 256) S->list[idx] = 0;
    }
    __syncthreads();
    const int mcount = S->mcount;

    // ---- Per-thread constants ----
    const float wr0_lo = W_r[lane],        wr0_hi = W_r[lane + 32];
    const float wr1_lo = W_r[64 + lane],   wr1_hi = W_r[64 + lane + 32];
    const float br_lo  = b_r[lane],        br_hi  = b_r[lane + 32];
    const float gr_lo  = g_r[lane],        gr_hi  = g_r[lane + 32];
    const float ber_lo = be_r[lane],       ber_hi = be_r[lane + 32];
    const float gg_lo  = g_g[lane],        gg_hi  = g_g[lane + 32];
    const float beg_lo = be_g[lane],       beg_hi = be_g[lane + 32];
    const float A_lo   = g_A[i * DD + lane];
    const float A_hi   = g_A[i * DD + lane + 32];
    const float S0 = g_S[0], S1 = g_S[1], Sb = g_S[2];
    const float Q00 = g_S[3], Q11 = g_S[4], Q01 = g_S[5];
    const float Q0b = g_S[6], Q1b = g_S[7], Qbb = g_S[8];

    const float2* corr2 = (const float2*)corr + (size_t)i * NN;

    float acc_lo = 0.f, acc_hi = 0.f;

    for (int base = warp * 8; base < mcount; base += 64) {
        float yl[8], yh[8];

        // ---- Phase 1: r vectors (analytic LN) -> shared, jj-interleaved ----
#pragma unroll
        for (int jj = 0; jj < 8; jj++) {
            const int j = S->list[base + jj];
            const float2 c = corr2[j];
            const float z_lo = fmaf(c.x, wr0_lo, fmaf(c.y, wr1_lo, br_lo));
            const float z_hi = fmaf(c.x, wr0_hi, fmaf(c.y, wr1_hi, br_hi));
            const float u   = fmaf(c.x, S0, fmaf(c.y, S1, Sb));
            const float ez2 = fmaf(c.x * c.x, Q00,
                              fmaf(c.y * c.y, Q11,
                              fmaf(2.f * c.x * c.y, Q01,
                              fmaf(2.f * c.x, Q0b,
                              fmaf(2.f * c.y, Q1b, Qbb)))));
            const float rstd = rsqrtf(fmaxf(ez2 - u * u, 0.f) + LN_EPS);
            float* Rp = S->Rsm[warp][jj >> 1];
            Rp[lane * 2 + (jj & 1)]        = fmaxf(fmaf(gr_lo * (z_lo - u), rstd, ber_lo), 0.f);
            Rp[(lane + 32) * 2 + (jj & 1)] = fmaxf(fmaf(gr_hi * (z_hi - u), rstd, ber_hi), 0.f);
            yl[jj] = A_lo + g_B[j * DD + lane];
            yh[jj] = A_hi + g_B[j * DD + lane + 32];
        }
        __syncwarp();

        unsigned long long ylo[4], yhi[4];
#pragma unroll
        for (int jp = 0; jp < 4; jp++) {
            PACK2(ylo[jp], yl[2 * jp], yl[2 * jp + 1]);
            PACK2(yhi[jp], yh[2 * jp], yh[2 * jp + 1]);
        }

        // ---- Phase 2: pure LDS + FFMA2, zero MOVs ----
#pragma unroll 4
        for (int k2 = 0; k2 < 32; k2++) {
            const ulonglong2 w0 = S->wdup[2 * k2][lane];      // k = 2k2
            const ulonglong2 w1 = S->wdup[2 * k2 + 1][lane];  // k = 2k2+1
#pragma unroll
            for (int jp = 0; jp < 4; jp++) {
                const ulonglong2 r = *(const ulonglong2*)&S->Rsm[warp][jp][k2 * 4];
                // r.x = (r[jj0][2k2], r[jj1][2k2]); r.y = same for 2k2+1
                FFMA2(ylo[jp], r.x, w0.x);
                FFMA2(yhi[jp], r.x, w0.y);
                FFMA2(ylo[jp], r.y, w1.x);
                FFMA2(yhi[jp], r.y, w1.y);
            }
        }
        __syncwarp();

        // ---- Phase 3: LN + sigmoid gate + accumulate ----
#pragma unroll
        for (int jp = 0; jp < 4; jp++) {
            float yl0, yl1, yh0, yh1;
            UNPACK2(yl0, yl1, ylo[jp]);
            UNPACK2(yh0, yh1, yhi[jp]);
#pragma unroll
            for (int p = 0; p < 2; p++) {
                const int jj = 2 * jp + p;
                if (base + jj >= mcount) continue;   // warp-uniform
                const float y_lo = p ? yl1 : yl0;
                const float y_hi = p ? yh1 : yh0;
                float s1 = y_lo + y_hi;
                float s2 = y_lo * y_lo + y_hi * y_hi;
#pragma unroll
                for (int off = 16; off; off >>= 1) {
                    s1 += __shfl_xor_sync(0xffffffffu, s1, off);
                    s2 += __shfl_xor_sync(0xffffffffu, s2, off);
                }
                const float u    = s1 * (1.f / 64.f);
                const float rstd = rsqrtf(fmaxf(s2 * (1.f / 64.f) - u * u, 0.f) + LN_EPS);
                const float t_lo = fmaf(gg_lo * (y_lo - u), rstd, beg_lo);
                const float t_hi = fmaf(gg_hi * (y_hi - u), rstd, beg_hi);
                const float gate_lo = 1.f / (1.f + __expf(-t_lo));
                const float gate_hi = 1.f / (1.f + __expf(-t_hi));
                const int j = S->list[base + jj];
                acc_lo = fmaf(h[j * DD + lane],      gate_lo, acc_lo);
                acc_hi = fmaf(h[j * DD + lane + 32], gate_hi, acc_hi);
            }
        }
    }

    S->sh_acc[warp][lane]      = acc_lo;
    S->sh_acc[warp][lane + 32] = acc_hi;
    __syncthreads();

    // ---- Block reduce + Pos scale ----
    if (tid < 64) {
        float s = 0.f;
#pragma unroll
        for (int w = 0; w < 8; w++) s += S->sh_acc[w][tid];
        const float rba   = fmaxf(be_a[0], 0.f);
        const float scale = (rba > 0.f) ? (1.f / (float)(mcount > 0 ? mcount : 1))
                                        : (1.f / (float)NN);
        S->sh_hs[tid] = s * scale;
    }
    __syncthreads();

    // ---- Epilogue ----
    if (tid < 64) {
        float y = b_w[tid];
#pragma unroll 16
        for (int k = 0; k < 64; k++)
            y = fmaf(S->sh_hs[k], W_w[k * DD + tid], y);
        S->sh_y[tid] = y;
    }
    __syncthreads();

    if (tid < 64) {
        float s1 = 0.f, s2 = 0.f;
#pragma unroll 16
        for (int k = 0; k < 64; k++) {
            const float v = S->sh_y[k];
            s1 += v;
            s2 += v * v;
        }
        const float u    = s1 * (1.f / 64.f);
        const float rstd = rsqrtf(fmaxf(s2 * (1.f / 64.f) - u * u, 0.f) + LN_EPS);
        const float y    = S->sh_y[tid];
        const float hsum = fmaxf(fmaf(g_w[tid] * (y - u), rstd, be_w[tid]), 0.f);
        const float Cv   = hsum + cn[i * DD + tid];
        const float Hout = h[i * DD + tid] + tanhf(Cv);
        out[i * DD + tid]           = Hout;
        out[NN * DD + i * DD + tid] = Cv;
    }
}

// ---------------------------------------------------------------------------
extern "C" void kernel_launch(void* const* d_in, const int* in_sizes, int n_in,
                              void* d_out, int out_size)
{
    const float* corr = (const float*)d_in[0];
    const int*   nei  = (const int*)d_in[1];
    const float* h    = (const float*)d_in[3];
    const float* cn   = (const float*)d_in[4];
    const float* W_r  = (const float*)d_in[5];
    const float* b_r  = (const float*)d_in[6];
    const float* g_r  = (const float*)d_in[7];
    const float* be_r = (const float*)d_in[8];
    const float* W_g  = (const float*)d_in[9];
    const float* b_g  = (const float*)d_in[10];
    const float* g_g  = (const float*)d_in[11];
    const float* be_g = (const float*)d_in[12];
    const float* be_a = (const float*)d_in[16];
    const float* W_w  = (const float*)d_in[17];
    const float* b_w  = (const float*)d_in[18];
    const float* g_w  = (const float*)d_in[19];
    const float* be_w = (const float*)d_in[20];
    float* out = (float*)d_out;

    const int smem_bytes = (int)sizeof(Smem);
    cudaFuncSetAttribute(gatraj_main_kernel,
                         cudaFuncAttributeMaxDynamicSharedMemorySize, smem_bytes);

    precompute_kernel<<<NN, DD>>>(h, W_g, b_g, W_r, b_r);
    gatraj_main_kernel<<<NN, 256, smem_bytes>>>(corr, nei, h, cn,
                                                W_r, b_r, g_r, be_r,
                                                W_g, g_g, be_g, be_a,
                                                W_w, b_w, g_w, be_w, out);
}

// round 8
// speedup vs baseline: 1.1514x; 1.0769x over previous
#include <cuda_runtime.h>
#include <cstdint>

#define NN 768
#define DD 64
#define LN_EPS 1e-5f

__device__ float g_A[NN * DD];  // h[i] @ W_g[64:128]
__device__ float g_B[NN * DD];  // h[j] @ W_g[128:192] + b_g
__device__ float g_S[9];        // LN(z) moment scalars (scaled by 1/64)

#define FFMA2(d, a, b) asm("fma.rn.f32x2 %0, %1, %2, %0;" : "+l"(d) : "l"(a), "l"(b))
#define PACK2(dst, lo, hi) asm("mov.b64 %0, {%1, %2};" : "=l"(dst) : "f"(lo), "f"(hi))
#define DUP2(dst, v)       asm("mov.b64 %0, {%1, %1};" : "=l"(dst) : "f"(v))
#define UNPACK2(lo, hi, v) asm("mov.b64 {%0, %1}, %2;" : "=f"(lo), "=f"(hi) : "l"(v))

// ---------------------------------------------------------------------------
// Precompute A[i,d], B[i,d], and the 9 LN(z) moment scalars
// ---------------------------------------------------------------------------
__global__ __launch_bounds__(DD) void precompute_kernel(
    const float* __restrict__ h,
    const float* __restrict__ W_g,
    const float* __restrict__ b_g,
    const float* __restrict__ W_r,
    const float* __restrict__ b_r)
{
    __shared__ float hs[DD];
    const int i = blockIdx.x;
    const int d = threadIdx.x;
    hs[d] = h[i * DD + d];
    __syncthreads();
    float a = 0.f, b = 0.f;
#pragma unroll 16
    for (int k = 0; k < DD; k++) {
        float hv = hs[k];
        a = fmaf(hv, W_g[(64 + k) * DD + d], a);
        b = fmaf(hv, W_g[(128 + k) * DD + d], b);
    }
    g_A[i * DD + d] = a;
    g_B[i * DD + d] = b + b_g[d];

    // Block 0: moment scalars for LN(corr @ W_r + b_r)
    if (i == 0) {
        const float w0 = W_r[d], w1 = W_r[64 + d], bb = b_r[d];
        float v[9] = { w0, w1, bb, w0 * w0, w1 * w1, w0 * w1,
                       w0 * bb, w1 * bb, bb * bb };
        __shared__ float red[2][9];
#pragma unroll
        for (int s = 0; s < 9; s++) {
            float x = v[s];
#pragma unroll
            for (int off = 16; off; off >>= 1)
                x += __shfl_xor_sync(0xffffffffu, x, off);
            v[s] = x;
        }
        if ((d & 31) == 0) {
#pragma unroll
            for (int s = 0; s < 9; s++) red[d >> 5][s] = v[s];
        }
        __syncthreads();
        if (d < 9) g_S[d] = (red[0][d] + red[1][d]) * (1.f / 64.f);
    }
}

// ---------------------------------------------------------------------------
// Main kernel: one block per row i; warps process chunks of 8 masked pairs.
// Lane owns output dims d=lane and d+32 (packed as f32x2).
// R5 structure, forced to 64 regs / 4 blocks per SM.
// ---------------------------------------------------------------------------
__global__ __launch_bounds__(256, 4) void gatraj_main_kernel(
    const float* __restrict__ corr,   // [N,N,2]
    const int*   __restrict__ nei,    // [N,N]
    const float* __restrict__ h,      // [N,D]
    const float* __restrict__ cn,     // [N,D]
    const float* __restrict__ W_r,    // [2,D]
    const float* __restrict__ b_r,
    const float* __restrict__ g_r,
    const float* __restrict__ be_r,
    const float* __restrict__ W_g,    // [3D,D] rows 0..63
    const float* __restrict__ g_g,
    const float* __restrict__ be_g,
    const float* __restrict__ be_a,   // [1]
    const float* __restrict__ W_w,    // [D,D]
    const float* __restrict__ b_w,
    const float* __restrict__ g_w,
    const float* __restrict__ be_w,
    float* __restrict__ out)          // [2*N*D]: H_out then C
{
    __shared__ unsigned long long wsm[64 * 32]; // (w[k][l], w[k][l+32])
    __shared__ float Rsm[8][8][64];             // [warp][jj][k]
    __shared__ int   list[832];
    __shared__ int   warp_tot[8], warp_off[8], mcount_sh;
    __shared__ float sh_acc[8][64];
    __shared__ float sh_hs[64];
    __shared__ float sh_y[64];

    const int i    = blockIdx.x;
    const int tid  = threadIdx.x;
    const int warp = tid >> 5;
    const int lane = tid & 31;

    const int* neirow = nei + (size_t)i * NN;

    // ---- Stage Wg_r as packed column pairs ----
    for (int idx = tid; idx < 64 * 32; idx += 256) {
        const int k = idx >> 5, l = idx & 31;
        unsigned long long w;
        PACK2(w, W_g[k * DD + l], W_g[k * DD + l + 32]);
        wsm[idx] = w;
    }

    // ---- Deterministic compaction of masked j (sorted order) ----
    {
        const int b3 = tid * 3;
        const int m0 = neirow[b3 + 0] > 0;
        const int m1 = neirow[b3 + 1] > 0;
        const int m2 = neirow[b3 + 2] > 0;
        const int c  = m0 + m1 + m2;
        int s = c;
#pragma unroll
        for (int off = 1; off < 32; off <<= 1) {
            int v = __shfl_up_sync(0xffffffffu, s, off);
            if (lane >= off) s += v;
        }
        if (lane == 31) warp_tot[warp] = s;
        __syncthreads();
        if (tid == 0) {
            int run = 0;
#pragma unroll
            for (int w = 0; w < 8; w++) { warp_off[w] = run; run += warp_tot[w]; }
            mcount_sh = run;
        }
        __syncthreads();
        int pos = warp_off[warp] + s - c;
        if (m0) list[pos++] = b3 + 0;
        if (m1) list[pos++] = b3 + 1;
        if (m2) list[pos++] = b3 + 2;
        const int mc  = mcount_sh;
        const int pad = (mc + 63) & ~63;
        for (int idx = mc + tid; idx < pad; idx += 256) list[idx] = 0;
    }
    __syncthreads();
    const int mcount = mcount_sh;

    // ---- Per-thread constants ----
    const float wr0_lo = W_r[lane],        wr0_hi = W_r[lane + 32];
    const float wr1_lo = W_r[64 + lane],   wr1_hi = W_r[64 + lane + 32];
    const float br_lo  = b_r[lane],        br_hi  = b_r[lane + 32];
    const float gr_lo  = g_r[lane],        gr_hi  = g_r[lane + 32];
    const float ber_lo = be_r[lane],       ber_hi = be_r[lane + 32];
    const float gg_lo  = g_g[lane],        gg_hi  = g_g[lane + 32];
    const float beg_lo = be_g[lane],       beg_hi = be_g[lane + 32];
    const float A_lo   = g_A[i * DD + lane];
    const float A_hi   = g_A[i * DD + lane + 32];
    // analytic LN(z) moment scalars
    const float S0 = g_S[0], S1 = g_S[1], Sb = g_S[2];
    const float Q00 = g_S[3], Q11 = g_S[4], Q01 = g_S[5];
    const float Q0b = g_S[6], Q1b = g_S[7], Qbb = g_S[8];

    const float2* corr2 = (const float2*)corr + (size_t)i * NN;

    float acc_lo = 0.f, acc_hi = 0.f;

    for (int base = warp * 8; base < mcount; base += 64) {
        unsigned long long yv[8];

        // ---- Phase 1: r vectors (shuffle-free analytic LN) -> shared; init y ----
#pragma unroll
        for (int jj = 0; jj < 8; jj++) {
            const int j = list[base + jj];
            const float2 c = corr2[j];
            const float z_lo = fmaf(c.x, wr0_lo, fmaf(c.y, wr1_lo, br_lo));
            const float z_hi = fmaf(c.x, wr0_hi, fmaf(c.y, wr1_hi, br_hi));
            const float u   = fmaf(c.x, S0, fmaf(c.y, S1, Sb));
            const float ez2 = fmaf(c.x * c.x, Q00,
                              fmaf(c.y * c.y, Q11,
                              fmaf(2.f * c.x * c.y, Q01,
                              fmaf(2.f * c.x, Q0b,
                              fmaf(2.f * c.y, Q1b, Qbb)))));
            const float rstd = rsqrtf(fmaxf(ez2 - u * u, 0.f) + LN_EPS);
            Rsm[warp][jj][lane]      = fmaxf(fmaf(gr_lo * (z_lo - u), rstd, ber_lo), 0.f);
            Rsm[warp][jj][lane + 32] = fmaxf(fmaf(gr_hi * (z_hi - u), rstd, ber_hi), 0.f);
            PACK2(yv[jj], A_lo + g_B[j * DD + lane], A_hi + g_B[j * DD + lane + 32]);
        }
        __syncwarp();

        // ---- Phase 2: y[jj] += r[jj] @ Wg_r (packed f32x2) ----
#pragma unroll 2
        for (int k4 = 0; k4 < 64; k4 += 4) {
            const unsigned long long w0 = wsm[(k4 + 0) * 32 + lane];
            const unsigned long long w1 = wsm[(k4 + 1) * 32 + lane];
            const unsigned long long w2 = wsm[(k4 + 2) * 32 + lane];
            const unsigned long long w3 = wsm[(k4 + 3) * 32 + lane];
#pragma unroll
            for (int jj = 0; jj < 8; jj++) {
                const float4 r4 = *(const float4*)&Rsm[warp][jj][k4]; // broadcast
                unsigned long long rr;
                DUP2(rr, r4.x); FFMA2(yv[jj], rr, w0);
                DUP2(rr, r4.y); FFMA2(yv[jj], rr, w1);
                DUP2(rr, r4.z); FFMA2(yv[jj], rr, w2);
                DUP2(rr, r4.w); FFMA2(yv[jj], rr, w3);
            }
        }
        __syncwarp();

        // ---- Phase 3: LN + sigmoid gate + accumulate ----
#pragma unroll
        for (int jj = 0; jj < 8; jj++) {
            if (base + jj >= mcount) break;    // warp-uniform
            float y_lo, y_hi;
            UNPACK2(y_lo, y_hi, yv[jj]);
            float s1 = y_lo + y_hi;
            float s2 = y_lo * y_lo + y_hi * y_hi;
#pragma unroll
            for (int off = 16; off; off >>= 1) {
                s1 += __shfl_xor_sync(0xffffffffu, s1, off);
                s2 += __shfl_xor_sync(0xffffffffu, s2, off);
            }
            const float u    = s1 * (1.f / 64.f);
            const float rstd = rsqrtf(fmaxf(s2 * (1.f / 64.f) - u * u, 0.f) + LN_EPS);
            const float t_lo = fmaf(gg_lo * (y_lo - u), rstd, beg_lo);
            const float t_hi = fmaf(gg_hi * (y_hi - u), rstd, beg_hi);
            const float gate_lo = 1.f / (1.f + __expf(-t_lo));
            const float gate_hi = 1.f / (1.f + __expf(-t_hi));
            const int j = list[base + jj];
            acc_lo = fmaf(h[j * DD + lane],      gate_lo, acc_lo);
            acc_hi = fmaf(h[j * DD + lane + 32], gate_hi, acc_hi);
        }
    }

    sh_acc[warp][lane]      = acc_lo;
    sh_acc[warp][lane + 32] = acc_hi;
    __syncthreads();

    // ---- Block reduce + Pos scale (Pos = 1/mcount if relu(be_a)>0 else 1/N) ----
    if (tid < 64) {
        float s = 0.f;
#pragma unroll
        for (int w = 0; w < 8; w++) s += sh_acc[w][tid];
        const float rba   = fmaxf(be_a[0], 0.f);
        const float scale = (rba > 0.f) ? (1.f / (float)(mcount > 0 ? mcount : 1))
                                        : (1.f / (float)NN);
        sh_hs[tid] = s * scale;
    }
    __syncthreads();

    // ---- Epilogue: relu(LN(H_sum @ W_w + b_w)) + cn; tanh ----
    if (tid < 64) {
        float y = b_w[tid];
#pragma unroll 16
        for (int k = 0; k < 64; k++)
            y = fmaf(sh_hs[k], W_w[k * DD + tid], y);
        sh_y[tid] = y;
    }
    __syncthreads();

    if (tid < 64) {
        float s1 = 0.f, s2 = 0.f;
#pragma unroll 16
        for (int k = 0; k < 64; k++) {
            const float v = sh_y[k];
            s1 += v;
            s2 += v * v;
        }
        const float u    = s1 * (1.f / 64.f);
        const float rstd = rsqrtf(fmaxf(s2 * (1.f / 64.f) - u * u, 0.f) + LN_EPS);
        const float y    = sh_y[tid];
        const float hsum = fmaxf(fmaf(g_w[tid] * (y - u), rstd, be_w[tid]), 0.f);
        const float Cv   = hsum + cn[i * DD + tid];
        const float Hout = h[i * DD + tid] + tanhf(Cv);
        out[i * DD + tid]           = Hout;
        out[NN * DD + i * DD + tid] = Cv;
    }
}

// ---------------------------------------------------------------------------
extern "C" void kernel_launch(void* const* d_in, const int* in_sizes, int n_in,
                              void* d_out, int out_size)
{
    const float* corr = (const float*)d_in[0];
    const int*   nei  = (const int*)d_in[1];
    const float* h    = (const float*)d_in[3];
    const float* cn   = (const float*)d_in[4];
    const float* W_r  = (const float*)d_in[5];
    const float* b_r  = (const float*)d_in[6];
    const float* g_r  = (const float*)d_in[7];
    const float* be_r = (const float*)d_in[8];
    const float* W_g  = (const float*)d_in[9];
    const float* b_g  = (const float*)d_in[10];
    const float* g_g  = (const float*)d_in[11];
    const float* be_g = (const float*)d_in[12];
    const float* be_a = (const float*)d_in[16];
    const float* W_w  = (const float*)d_in[17];
    const float* b_w  = (const float*)d_in[18];
    const float* g_w  = (const float*)d_in[19];
    const float* be_w = (const float*)d_in[20];
    float* out = (float*)d_out;

    precompute_kernel<<<NN, DD>>>(h, W_g, b_g, W_r, b_r);
    gatraj_main_kernel<<<NN, 256>>>(corr, nei, h, cn,
                                    W_r, b_r, g_r, be_r,
                                    W_g, g_g, be_g, be_a,
                                    W_w, b_w, g_w, be_w, out);
}

// round 9
// speedup vs baseline: 1.2590x; 1.0935x over previous
#include <cuda_runtime.h>
#include <cstdint>

#define NN 768
#define DD 64
#define LN_EPS 1e-5f

__device__ float g_A[NN * DD];  // h[i] @ W_g[64:128]
__device__ float g_B[NN * DD];  // h[j] @ W_g[128:192] + b_g
__device__ float g_S[9];        // LN(z) moment scalars (scaled by 1/64)

#define FFMA2(d, a, b) asm("fma.rn.f32x2 %0, %1, %2, %0;" : "+l"(d) : "l"(a), "l"(b))
#define PACK2(dst, lo, hi) asm("mov.b64 %0, {%1, %2};" : "=l"(dst) : "f"(lo), "f"(hi))
#define DUP2(dst, v)       asm("mov.b64 %0, {%1, %1};" : "=l"(dst) : "f"(v))
#define UNPACK2(lo, hi, v) asm("mov.b64 {%0, %1}, %2;" : "=f"(lo), "=f"(hi) : "l"(v))

// ---------------------------------------------------------------------------
// Precompute A[i,d], B[i,d], and the 9 LN(z) moment scalars
// ---------------------------------------------------------------------------
__global__ __launch_bounds__(DD) void precompute_kernel(
    const float* __restrict__ h,
    const float* __restrict__ W_g,
    const float* __restrict__ b_g,
    const float* __restrict__ W_r,
    const float* __restrict__ b_r)
{
    __shared__ float hs[DD];
    const int i = blockIdx.x;
    const int d = threadIdx.x;
    hs[d] = h[i * DD + d];
    __syncthreads();
    float a = 0.f, b = 0.f;
#pragma unroll 16
    for (int k = 0; k < DD; k++) {
        float hv = hs[k];
        a = fmaf(hv, W_g[(64 + k) * DD + d], a);
        b = fmaf(hv, W_g[(128 + k) * DD + d], b);
    }
    g_A[i * DD + d] = a;
    g_B[i * DD + d] = b + b_g[d];

    // Block 0: moment scalars for LN(corr @ W_r + b_r)
    if (i == 0) {
        const float w0 = W_r[d], w1 = W_r[64 + d], bb = b_r[d];
        float v[9] = { w0, w1, bb, w0 * w0, w1 * w1, w0 * w1,
                       w0 * bb, w1 * bb, bb * bb };
        __shared__ float red[2][9];
#pragma unroll
        for (int s = 0; s < 9; s++) {
            float x = v[s];
#pragma unroll
            for (int off = 16; off; off >>= 1)
                x += __shfl_xor_sync(0xffffffffu, x, off);
            v[s] = x;
        }
        if ((d & 31) == 0) {
#pragma unroll
            for (int s = 0; s < 9; s++) red[d >> 5][s] = v[s];
        }
        __syncthreads();
        if (d < 9) g_S[d] = (red[0][d] + red[1][d]) * (1.f / 64.f);
    }
}

// ---------------------------------------------------------------------------
// Main kernel: one block per row i; warps process chunks of 8 masked pairs.
// Lane owns output dims d=lane and d+32 (packed as f32x2).
// Phase 3 is branch-free across jj so the 16 shuffle chains interleave.
// ---------------------------------------------------------------------------
__global__ __launch_bounds__(256) void gatraj_main_kernel(
    const float* __restrict__ corr,   // [N,N,2]
    const int*   __restrict__ nei,    // [N,N]
    const float* __restrict__ h,      // [N,D]
    const float* __restrict__ cn,     // [N,D]
    const float* __restrict__ W_r,    // [2,D]
    const float* __restrict__ b_r,
    const float* __restrict__ g_r,
    const float* __restrict__ be_r,
    const float* __restrict__ W_g,    // [3D,D] rows 0..63
    const float* __restrict__ g_g,
    const float* __restrict__ be_g,
    const float* __restrict__ be_a,   // [1]
    const float* __restrict__ W_w,    // [D,D]
    const float* __restrict__ b_w,
    const float* __restrict__ g_w,
    const float* __restrict__ be_w,
    float* __restrict__ out)          // [2*N*D]: H_out then C
{
    __shared__ unsigned long long wsm[64 * 32]; // (w[k][l], w[k][l+32])
    __shared__ float Rsm[8][8][64];             // [warp][jj][k]
    __shared__ int   list[832];
    __shared__ int   warp_tot[8], warp_off[8], mcount_sh;
    __shared__ float sh_acc[8][64];
    __shared__ float sh_hs[64];
    __shared__ float sh_y[64];

    const int i    = blockIdx.x;
    const int tid  = threadIdx.x;
    const int warp = tid >> 5;
    const int lane = tid & 31;

    const int* neirow = nei + (size_t)i * NN;

    // ---- Stage Wg_r as packed column pairs ----
    for (int idx = tid; idx < 64 * 32; idx += 256) {
        const int k = idx >> 5, l = idx & 31;
        unsigned long long w;
        PACK2(w, W_g[k * DD + l], W_g[k * DD + l + 32]);
        wsm[idx] = w;
    }

    // ---- Deterministic compaction of masked j (sorted order) ----
    {
        const int b3 = tid * 3;
        const int m0 = neirow[b3 + 0] > 0;
        const int m1 = neirow[b3 + 1] > 0;
        const int m2 = neirow[b3 + 2] > 0;
        const int c  = m0 + m1 + m2;
        int s = c;
#pragma unroll
        for (int off = 1; off < 32; off <<= 1) {
            int v = __shfl_up_sync(0xffffffffu, s, off);
            if (lane >= off) s += v;
        }
        if (lane == 31) warp_tot[warp] = s;
        __syncthreads();
        if (tid == 0) {
            int run = 0;
#pragma unroll
            for (int w = 0; w < 8; w++) { warp_off[w] = run; run += warp_tot[w]; }
            mcount_sh = run;
        }
        __syncthreads();
        int pos = warp_off[warp] + s - c;
        if (m0) list[pos++] = b3 + 0;
        if (m1) list[pos++] = b3 + 1;
        if (m2) list[pos++] = b3 + 2;
        const int mc  = mcount_sh;
        const int pad = (mc + 63) & ~63;
        for (int idx = mc + tid; idx < pad; idx += 256) list[idx] = 0;
    }
    __syncthreads();
    const int mcount = mcount_sh;

    // ---- Per-thread constants ----
    const float wr0_lo = W_r[lane],        wr0_hi = W_r[lane + 32];
    const float wr1_lo = W_r[64 + lane],   wr1_hi = W_r[64 + lane + 32];
    const float br_lo  = b_r[lane],        br_hi  = b_r[lane + 32];
    const float gr_lo  = g_r[lane],        gr_hi  = g_r[lane + 32];
    const float ber_lo = be_r[lane],       ber_hi = be_r[lane + 32];
    const float gg_lo  = g_g[lane],        gg_hi  = g_g[lane + 32];
    const float beg_lo = be_g[lane],       beg_hi = be_g[lane + 32];
    const float A_lo   = g_A[i * DD + lane];
    const float A_hi   = g_A[i * DD + lane + 32];
    // analytic LN(z) moment scalars
    const float S0 = g_S[0], S1 = g_S[1], Sb = g_S[2];
    const float Q00 = g_S[3], Q11 = g_S[4], Q01 = g_S[5];
    const float Q0b = g_S[6], Q1b = g_S[7], Qbb = g_S[8];

    const float2* corr2 = (const float2*)corr + (size_t)i * NN;

    float acc_lo = 0.f, acc_hi = 0.f;

    for (int base = warp * 8; base < mcount; base += 64) {
        unsigned long long yv[8];

        // ---- Phase 1: r vectors (shuffle-free analytic LN) -> shared; init y ----
#pragma unroll
        for (int jj = 0; jj < 8; jj++) {
            const int j = list[base + jj];
            const float2 c = corr2[j];
            const float z_lo = fmaf(c.x, wr0_lo, fmaf(c.y, wr1_lo, br_lo));
            const float z_hi = fmaf(c.x, wr0_hi, fmaf(c.y, wr1_hi, br_hi));
            const float u   = fmaf(c.x, S0, fmaf(c.y, S1, Sb));
            const float ez2 = fmaf(c.x * c.x, Q00,
                              fmaf(c.y * c.y, Q11,
                              fmaf(2.f * c.x * c.y, Q01,
                              fmaf(2.f * c.x, Q0b,
                              fmaf(2.f * c.y, Q1b, Qbb)))));
            const float rstd = rsqrtf(fmaxf(ez2 - u * u, 0.f) + LN_EPS);
            Rsm[warp][jj][lane]      = fmaxf(fmaf(gr_lo * (z_lo - u), rstd, ber_lo), 0.f);
            Rsm[warp][jj][lane + 32] = fmaxf(fmaf(gr_hi * (z_hi - u), rstd, ber_hi), 0.f);
            PACK2(yv[jj], A_lo + g_B[j * DD + lane], A_hi + g_B[j * DD + lane + 32]);
        }
        __syncwarp();

        // ---- Phase 2: y[jj] += r[jj] @ Wg_r (packed f32x2) ----
#pragma unroll 2
        for (int k4 = 0; k4 < 64; k4 += 4) {
            const unsigned long long w0 = wsm[(k4 + 0) * 32 + lane];
            const unsigned long long w1 = wsm[(k4 + 1) * 32 + lane];
            const unsigned long long w2 = wsm[(k4 + 2) * 32 + lane];
            const unsigned long long w3 = wsm[(k4 + 3) * 32 + lane];
#pragma unroll
            for (int jj = 0; jj < 8; jj++) {
                const float4 r4 = *(const float4*)&Rsm[warp][jj][k4]; // broadcast
                unsigned long long rr;
                DUP2(rr, r4.x); FFMA2(yv[jj], rr, w0);
                DUP2(rr, r4.y); FFMA2(yv[jj], rr, w1);
                DUP2(rr, r4.z); FFMA2(yv[jj], rr, w2);
                DUP2(rr, r4.w); FFMA2(yv[jj], rr, w3);
            }
        }
        __syncwarp();

        // ---- Phase 3: LN + sigmoid gate + accumulate (branch-free, interleaved) ----
        float s1v[8], s2v[8];
#pragma unroll
        for (int jj = 0; jj < 8; jj++) {
            float y_lo, y_hi;
            UNPACK2(y_lo, y_hi, yv[jj]);
            s1v[jj] = y_lo + y_hi;
            s2v[jj] = y_lo * y_lo + y_hi * y_hi;
        }
        // 16 independent butterfly chains — fully interleavable
#pragma unroll
        for (int off = 16; off; off >>= 1) {
#pragma unroll
            for (int jj = 0; jj < 8; jj++) {
                s1v[jj] += __shfl_xor_sync(0xffffffffu, s1v[jj], off);
                s2v[jj] += __shfl_xor_sync(0xffffffffu, s2v[jj], off);
            }
        }
#pragma unroll
        for (int jj = 0; jj < 8; jj++) {
            float y_lo, y_hi;
            UNPACK2(y_lo, y_hi, yv[jj]);
            const float u    = s1v[jj] * (1.f / 64.f);
            const float rstd = rsqrtf(fmaxf(s2v[jj] * (1.f / 64.f) - u * u, 0.f) + LN_EPS);
            const float t_lo = fmaf(gg_lo * (y_lo - u), rstd, beg_lo);
            const float t_hi = fmaf(gg_hi * (y_hi - u), rstd, beg_hi);
            const float gate_lo = 1.f / (1.f + __expf(-t_lo));
            const float gate_hi = 1.f / (1.f + __expf(-t_hi));
            const int j = list[base + jj];
            const float hj_lo = h[j * DD + lane];
            const float hj_hi = h[j * DD + lane + 32];
            if (base + jj < mcount) {           // predicated accumulate only
                acc_lo = fmaf(hj_lo, gate_lo, acc_lo);
                acc_hi = fmaf(hj_hi, gate_hi, acc_hi);
            }
        }
    }

    sh_acc[warp][lane]      = acc_lo;
    sh_acc[warp][lane + 32] = acc_hi;
    __syncthreads();

    // ---- Block reduce + Pos scale (Pos = 1/mcount if relu(be_a)>0 else 1/N) ----
    if (tid < 64) {
        float s = 0.f;
#pragma unroll
        for (int w = 0; w < 8; w++) s += sh_acc[w][tid];
        const float rba   = fmaxf(be_a[0], 0.f);
        const float scale = (rba > 0.f) ? (1.f / (float)(mcount > 0 ? mcount : 1))
                                        : (1.f / (float)NN);
        sh_hs[tid] = s * scale;
    }
    __syncthreads();

    // ---- Epilogue: relu(LN(H_sum @ W_w + b_w)) + cn; tanh ----
    if (tid < 64) {
        float y = b_w[tid];
#pragma unroll 16
        for (int k = 0; k < 64; k++)
            y = fmaf(sh_hs[k], W_w[k * DD + tid], y);
        sh_y[tid] = y;
    }
    __syncthreads();

    if (tid < 64) {
        float s1 = 0.f, s2 = 0.f;
#pragma unroll 16
        for (int k = 0; k < 64; k++) {
            const float v = sh_y[k];
            s1 += v;
            s2 += v * v;
        }
        const float u    = s1 * (1.f / 64.f);
        const float rstd = rsqrtf(fmaxf(s2 * (1.f / 64.f) - u * u, 0.f) + LN_EPS);
        const float y    = sh_y[tid];
        const float hsum = fmaxf(fmaf(g_w[tid] * (y - u), rstd, be_w[tid]), 0.f);
        const float Cv   = hsum + cn[i * DD + tid];
        const float Hout = h[i * DD + tid] + tanhf(Cv);
        out[i * DD + tid]           = Hout;
        out[NN * DD + i * DD + tid] = Cv;
    }
}

// ---------------------------------------------------------------------------
extern "C" void kernel_launch(void* const* d_in, const int* in_sizes, int n_in,
                              void* d_out, int out_size)
{
    const float* corr = (const float*)d_in[0];
    const int*   nei  = (const int*)d_in[1];
    const float* h    = (const float*)d_in[3];
    const float* cn   = (const float*)d_in[4];
    const float* W_r  = (const float*)d_in[5];
    const float* b_r  = (const float*)d_in[6];
    const float* g_r  = (const float*)d_in[7];
    const float* be_r = (const float*)d_in[8];
    const float* W_g  = (const float*)d_in[9];
    const float* b_g  = (const float*)d_in[10];
    const float* g_g  = (const float*)d_in[11];
    const float* be_g = (const float*)d_in[12];
    const float* be_a = (const float*)d_in[16];
    const float* W_w  = (const float*)d_in[17];
    const float* b_w  = (const float*)d_in[18];
    const float* g_w  = (const float*)d_in[19];
    const float* be_w = (const float*)d_in[20];
    float* out = (float*)d_out;

    precompute_kernel<<<NN, DD>>>(h, W_g, b_g, W_r, b_r);
    gatraj_main_kernel<<<NN, 256>>>(corr, nei, h, cn,
                                    W_r, b_r, g_r, be_r,
                                    W_g, g_g, be_g, be_a,
                                    W_w, b_w, g_w, be_w, out);
}